// round 7
// baseline (speedup 1.0000x reference)
#include <cuda_runtime.h>
#include <math.h>
#include <float.h>

#define HH 512
#define WW 512
#define NS 5000
#define SS 10
#define NSEG 9
#define KK 20
#define HC 102
#define WC 102
#define NCELL (HC*WC)

#define GB 32              // bins per axis
#define NBIN (GB*GB)       // 1024
#define BINW 16.0f         // bin width in px
#define INV_BINW 0.0625f

// Scratch (static device globals — no runtime allocation)
__device__ float4 g_seg[NS*NSEG];    // per segment: ax, ay, dx, dy
__device__ float  g_sinv[NS*NSEG];   // per segment: 1/(dx^2+dy^2)
__device__ float4 g_col4[NS];        // stroke color (padded)
__device__ int    g_binoff[NBIN+1];  // bin start offsets (exclusive scan)
__device__ float2 g_bloc[NS];        // stroke locations, grouped by bin
__device__ int    g_bidx[NS];        // stroke indices,  grouped by bin
__device__ int    g_cidx[NCELL*KK];  // per coarse cell: sorted top-K stroke indices
__device__ float  g_cw[NCELL*KK];    // per coarse cell: widths (rank-aligned)

// ---------------------------------------------------------------------------
// Kernel 1: block 0 builds the spatial bin structure (count + shuffle scan +
// scatter). Blocks 1..5 do bezier -> segment precompute and pack colors.
// ---------------------------------------------------------------------------
__global__ __launch_bounds__(1024) void build_kernel(
    const float* __restrict__ cs,
    const float* __restrict__ ce,
    const float* __restrict__ cc,
    const float* __restrict__ loc,
    const float* __restrict__ color)
{
    int tid = threadIdx.x;

    if (blockIdx.x == 0) {
        __shared__ int s_cnt[NBIN];     // counts, then running cursors
        __shared__ int s_wsum[32];      // per-warp partial sums

        s_cnt[tid] = 0;
        __syncthreads();

        // count
        for (int i = tid; i < NS; i += 1024) {
            float x = loc[2*i], y = loc[2*i+1];
            int bx = min(GB-1, (int)(x * INV_BINW));
            int by = min(GB-1, (int)(y * INV_BINW));
            atomicAdd(&s_cnt[bx*GB + by], 1);
        }
        __syncthreads();

        // shuffle-based inclusive scan over 1024 bins
        int lane = tid & 31, warp = tid >> 5;
        int v = s_cnt[tid];
        int incl = v;
#pragma unroll
        for (int off = 1; off < 32; off <<= 1) {
            int u = __shfl_up_sync(0xffffffffu, incl, off);
            if (lane >= off) incl += u;
        }
        if (lane == 31) s_wsum[warp] = incl;
        __syncthreads();
        if (warp == 0) {
            int wv = s_wsum[lane];
            int wincl = wv;
#pragma unroll
            for (int off = 1; off < 32; off <<= 1) {
                int u = __shfl_up_sync(0xffffffffu, wincl, off);
                if (lane >= off) wincl += u;
            }
            s_wsum[lane] = wincl - wv;   // exclusive warp offsets
        }
        __syncthreads();
        int excl = incl - v + s_wsum[warp];
        g_binoff[tid] = excl;
        if (tid == NBIN-1) g_binoff[NBIN] = excl + v;
        s_cnt[tid] = excl;               // running cursor
        __syncthreads();

        // scatter
        for (int i = tid; i < NS; i += 1024) {
            float x = loc[2*i], y = loc[2*i+1];
            int bx = min(GB-1, (int)(x * INV_BINW));
            int by = min(GB-1, (int)(y * INV_BINW));
            int pos = atomicAdd(&s_cnt[bx*GB + by], 1);
            g_bloc[pos] = make_float2(x, y);
            g_bidx[pos] = i;
        }
        return;
    }

    // ---------------- bezier + segment precompute + color pack ----------------
    int n = (blockIdx.x - 1) * 1024 + tid;
    if (n >= NS) return;
    float lx = loc[2*n], ly = loc[2*n+1];
    float sx = cs[2*n] + lx, sy = cs[2*n+1] + ly;
    float cx = cc[2*n] + lx, cy = cc[2*n+1] + ly;
    float ex = ce[2*n] + lx, ey = ce[2*n+1] + ly;
    float dsx = sx - cx, dsy = sy - cy;
    float dex = ex - cx, dey = ey - cy;
    const float dt = 1.0f / 9.0f;
    float pxp[SS], pyp[SS];
#pragma unroll
    for (int j = 0; j < SS; j++) {
        float t   = (float)j * dt;
        float omt = 1.0f - t;
        float o2  = omt * omt;
        float t2  = t * t;
        pxp[j] = cx + o2 * dsx + t2 * dex;
        pyp[j] = cy + o2 * dsy + t2 * dey;
    }
#pragma unroll
    for (int s = 0; s < NSEG; s++) {
        float ax = pxp[s],      ay = pyp[s];
        float dx = pxp[s+1]-ax, dy = pyp[s+1]-ay;
        float denom = dx*dx + dy*dy;
        g_seg[n*NSEG + s]  = make_float4(ax, ay, dx, dy);
        g_sinv[n*NSEG + s] = 1.0f / denom;
    }
    g_col4[n] = make_float4(color[n*3], color[n*3+1], color[n*3+2], 0.0f);
}

// ---------------------------------------------------------------------------
// Kernel 2: per-coarse-cell exact top-K — WARP-UNIFORM grid ring walk.
// Warp owns an 8(cj) x 4(ci) cell patch; lane = one cell. The bin walk is
// identical for all lanes (bbox = warp-reduced min/max bin), so candidate
// loads are uniform-address broadcasts and there is no divergence
// serialization. Lexicographic (dist, idx) keys => exact JAX top_k order.
// ---------------------------------------------------------------------------
__global__ __launch_bounds__(128) void topk_kernel(const float* __restrict__ width)
{
    int lane = threadIdx.x & 31;
    int wid  = threadIdx.x >> 5;     // 0..3
    int wx   = wid & 1;              // cj patch selector (2 per block)
    int wy   = wid >> 1;             // ci patch selector (2 per block)
    int lj   = lane & 7;             // 0..7  (cj within patch)
    int li   = lane >> 3;            // 0..3  (ci within patch)

    int ci = blockIdx.y * 8  + wy * 4 + li;
    int cj = blockIdx.x * 16 + wx * 8 + lj;
    bool valid = (ci < HC) && (cj < WC);
    int cic = min(ci, HC-1);
    int cjc = min(cj, WC-1);

    const float STEPC = 512.0f / 101.0f;
    float px = (float)cic * STEPC;
    float py = (float)cjc * STEPC;

    float bd[KK];
    int   bi[KK];
#pragma unroll
    for (int k = 0; k < KK; k++) { bd[k] = FLT_MAX; bi[k] = 0x7fffffff; }

    int bx = min(GB-1, (int)(px * INV_BINW));
    int by = min(GB-1, (int)(py * INV_BINW));

    // warp-uniform bin bbox
    int bxmin = (int)__reduce_min_sync(0xffffffffu, (unsigned)bx);
    int bxmax = (int)__reduce_max_sync(0xffffffffu, (unsigned)bx);
    int bymin = (int)__reduce_min_sync(0xffffffffu, (unsigned)by);
    int bymax = (int)__reduce_max_sync(0xffffffffu, (unsigned)by);

    for (int r = 0; r < GB; r++) {
        int x0 = bxmin - r, x1 = bxmax + r;
        int y0 = bymin - r, y1 = bymax + r;
        int cx0 = max(x0, 0), cx1 = min(x1, GB-1);
        int cy0 = max(y0, 0), cy1 = min(y1, GB-1);

        for (int xx = cx0; xx <= cx1; xx++) {
            bool xinterior = (r > 0) && (xx > x0) && (xx < x1);
            for (int yy = cy0; yy <= cy1; yy++) {
                if (xinterior && yy > y0 && yy < y1) continue;  // done at ring r-1
                int b  = xx*GB + yy;
                int s0 = g_binoff[b];
                int s1 = g_binoff[b+1];
                for (int j = s0; j < s1; j++) {
                    float2 L = g_bloc[j];      // uniform address -> broadcast
                    int idx  = g_bidx[j];
                    float dx = px - L.x, dy = py - L.y;
                    float d  = dx*dx + dy*dy;
                    if (__any_sync(0xffffffffu,
                                   d < bd[KK-1] || (d == bd[KK-1] && idx < bi[KK-1]))) {
                        float pd = d; int pi = idx;
                        bool lock = !(d < bd[KK-1] || (d == bd[KK-1] && idx < bi[KK-1]));
#pragma unroll
                        for (int k = 0; k < KK; k++) {
                            bool c = !lock && ((pd < bd[k]) || (pd == bd[k] && pi < bi[k]));
                            float od = bd[k]; int oi = bi[k];
                            bd[k] = c ? pd : od;  bi[k] = c ? pi : oi;
                            pd    = c ? od : pd;  pi    = c ? oi : pi;
                        }
                    }
                }
            }
        }

        // exact termination: everything unprocessed lies outside the swept
        // (unclamped) rectangle => distance >= m for this lane
        float m = fminf(fminf(px - (float)x0 * BINW, (float)(x1+1) * BINW - px),
                        fminf(py - (float)y0 * BINW, (float)(y1+1) * BINW - py));
        bool done = bd[KK-1] < m * m;
        if (__all_sync(0xffffffffu, done)) break;
    }

    if (valid) {
        int cell = ci * WC + cj;
#pragma unroll
        for (int o = 0; o < KK; o++) {
            g_cidx[cell*KK + o] = bi[o];
            g_cw  [cell*KK + o] = width[bi[o]];
        }
    }
}

// ---------------------------------------------------------------------------
// Kernel 3: per-pixel render. Branch-free streaming softmax.
// ---------------------------------------------------------------------------
__global__ __launch_bounds__(256, 5) void render_kernel(float* __restrict__ out)
{
    int w = blockIdx.x * 8  + threadIdx.x;
    int h = blockIdx.y * 32 + threadIdx.y;

    const float STEPF = 512.0f / 511.0f;
    float px = (float)h * STEPF;
    float py = (float)w * STEPF;

    const float SC = 102.0f / 512.0f;      // exact in fp32
    int ihc = (int)floorf((float)h * SC); if (ihc > HC-1) ihc = HC-1;
    int iwc = (int)floorf((float)w * SC); if (iwc > WC-1) iwc = WC-1;
    int cell = ihc * WC + iwc;

    // bilinear coords for width resize (half-pixel convention, edge clamp)
    float uh = ((float)h + 0.5f) * SC - 0.5f;
    uh = fminf(fmaxf(uh, 0.0f), (float)(HC-1));
    int h0 = (int)uh; float fh = uh - (float)h0; int h1 = min(h0+1, HC-1);
    float uw = ((float)w + 0.5f) * SC - 0.5f;
    uw = fminf(fmaxf(uw, 0.0f), (float)(WC-1));
    int w0 = (int)uw; float fw = uw - (float)w0; int w1 = min(w0+1, WC-1);

    float c00 = (1.0f - fh) * (1.0f - fw);
    float c01 = (1.0f - fh) * fw;
    float c10 = fh * (1.0f - fw);
    float c11 = fh * fw;

    const float* W00 = &g_cw[(h0*WC + w0)*KK];
    const float* W01 = &g_cw[(h0*WC + w1)*KK];
    const float* W10 = &g_cw[(h1*WC + w0)*KK];
    const float* W11 = &g_cw[(h1*WC + w1)*KK];
    const int*   IDX = &g_cidx[cell*KK];

    float M = -FLT_MAX, ssum = 0.0f;
    float a0 = 0.0f, a1 = 0.0f, a2 = 0.0f, bsacc = 0.0f;
    float Dmin = FLT_MAX;

    for (int k = 0; k < KK; k++) {
        int n = __ldg(&IDX[k]);
        const float4* S4 = &g_seg[n*NSEG];
        const float*  SI = &g_sinv[n*NSEG];
        float md = FLT_MAX;
#pragma unroll
        for (int s = 0; s < NSEG; s++) {
            float4 sg = __ldg(&S4[s]);
            float inv = __ldg(&SI[s]);
            float pax = px - sg.x, pay = py - sg.y;
            float t = (sg.z*pax + sg.w*pay) * inv;
            t = fminf(fmaxf(t, 0.0f), 1.0f);
            float cx = sg.x + t*sg.z;
            float cy = sg.y + t*sg.w;
            float dx = px - cx, dy = py - cy;
            md = fminf(md, dx*dx + dy*dy);
        }
        Dmin = fminf(Dmin, md);
        float L = 100000.0f / (1e-8f + md);   // exact div: softmax-sensitive

        float wk = c00 * __ldg(&W00[k]) + c01 * __ldg(&W01[k])
                 + c10 * __ldg(&W10[k]) + c11 * __ldg(&W11[k]);

        float4 col = __ldg(&g_col4[n]);

        float nM = fmaxf(M, L);
        float rr = __expf(M - nM);            // 1.0 when M unchanged
        float e  = __expf(L - nM);
        ssum  = ssum  * rr + e;
        a0    = a0    * rr + e * col.x;
        a1    = a1    * rr + e * col.y;
        a2    = a2    * rr + e * col.z;
        bsacc = bsacc * rr + e * wk;
        M = nM;
    }

    float inv = 1.0f / ssum;
    float bs  = bsacc * inv;
    float x   = bs - Dmin;
    float mask = 1.0f / (1.0f + expf(-x));
    float omm  = 1.0f - mask;

    int base = (h*WW + w) * 3;
    out[base + 0] = a0 * inv * mask + omm * 0.5f;
    out[base + 1] = a1 * inv * mask + omm * 0.5f;
    out[base + 2] = a2 * inv * mask + omm * 0.5f;
}

// ---------------------------------------------------------------------------
// Launch. Inputs (metadata order): curve_s, curve_e, curve_c, color, location, width
// ---------------------------------------------------------------------------
extern "C" void kernel_launch(void* const* d_in, const int* in_sizes, int n_in,
                              void* d_out, int out_size)
{
    const float* curve_s  = (const float*)d_in[0];
    const float* curve_e  = (const float*)d_in[1];
    const float* curve_c  = (const float*)d_in[2];
    const float* color    = (const float*)d_in[3];
    const float* location = (const float*)d_in[4];
    const float* width    = (const float*)d_in[5];
    float* out = (float*)d_out;

    // block 0: spatial binning; blocks 1..5: bezier/segment/color precompute
    build_kernel<<<1 + (NS + 1023)/1024, 1024>>>(curve_s, curve_e, curve_c,
                                                 location, color);

    // warp = 8x4 cell patch; block = 128 thr = 16(cj) x 8(ci) cells
    dim3 tgrd((WC + 15)/16, (HC + 7)/8);
    topk_kernel<<<tgrd, 128>>>(width);

    dim3 blk(8, 32);
    dim3 grd(WW/8, HH/32);
    render_kernel<<<grd, blk>>>(out);
}

// round 10
// speedup vs baseline: 1.3757x; 1.3757x over previous
#include <cuda_runtime.h>
#include <math.h>
#include <float.h>

#define HH 512
#define WW 512
#define NS 5000
#define SS 10
#define NSEG 9
#define KK 20
#define HC 102
#define WC 102
#define NCELL (HC*WC)

#define GB 32              // bins per axis
#define NBIN (GB*GB)       // 1024
#define BINW 16.0f         // bin width in px
#define INV_BINW 0.0625f
#define STEPC (512.0f/101.0f)

#define PATCH 8                              // topk: 8x8 cells per block
#define TGX ((HC + PATCH - 1)/PATCH)         // 13
#define TPATCH (TGX*TGX)                     // 169 patch blocks
#define BEZB ((NS + 63)/64)                  // 79 bezier blocks
#define MARGIN 4                             // bins of margin => m >= 64 px
#define MAXCAND 1024

// Scratch (static device globals — no runtime allocation)
__device__ float4 g_seg[NS*NSEG];    // per segment: ax, ay, dx, dy
__device__ float  g_sinv[NS*NSEG];   // per segment: 1/(dx^2+dy^2)
__device__ float4 g_col4[NS];        // stroke color (padded)
__device__ int    g_binoff[NBIN+1];  // bin start offsets (exclusive scan)
__device__ float4 g_bpack[NS];       // binned strokes: x, y, bitcast(idx), pad
__device__ int    g_cidx[NCELL*KK];  // per coarse cell: sorted top-K stroke indices
__device__ float  g_cw[NCELL*KK];    // per coarse cell: widths (rank-aligned)

// ---------------------------------------------------------------------------
// Kernel 1: spatial binning (single block: count + shuffle scan + scatter).
// ---------------------------------------------------------------------------
__global__ __launch_bounds__(1024) void bin_kernel(const float* __restrict__ loc)
{
    __shared__ int s_cnt[NBIN];
    __shared__ int s_wsum[32];
    int tid = threadIdx.x;

    s_cnt[tid] = 0;
    __syncthreads();

    for (int i = tid; i < NS; i += 1024) {
        float x = loc[2*i], y = loc[2*i+1];
        int bx = min(GB-1, (int)(x * INV_BINW));
        int by = min(GB-1, (int)(y * INV_BINW));
        atomicAdd(&s_cnt[bx*GB + by], 1);
    }
    __syncthreads();

    int lane = tid & 31, warp = tid >> 5;
    int v = s_cnt[tid];
    int incl = v;
#pragma unroll
    for (int off = 1; off < 32; off <<= 1) {
        int u = __shfl_up_sync(0xffffffffu, incl, off);
        if (lane >= off) incl += u;
    }
    if (lane == 31) s_wsum[warp] = incl;
    __syncthreads();
    if (warp == 0) {
        int wv = s_wsum[lane];
        int wincl = wv;
#pragma unroll
        for (int off = 1; off < 32; off <<= 1) {
            int u = __shfl_up_sync(0xffffffffu, wincl, off);
            if (lane >= off) wincl += u;
        }
        s_wsum[lane] = wincl - wv;
    }
    __syncthreads();
    int excl = incl - v + s_wsum[warp];
    g_binoff[tid] = excl;
    if (tid == NBIN-1) g_binoff[NBIN] = excl + v;
    s_cnt[tid] = excl;
    __syncthreads();

    for (int i = tid; i < NS; i += 1024) {
        float x = loc[2*i], y = loc[2*i+1];
        int bx = min(GB-1, (int)(x * INV_BINW));
        int by = min(GB-1, (int)(y * INV_BINW));
        int pos = atomicAdd(&s_cnt[bx*GB + by], 1);
        g_bpack[pos] = make_float4(x, y, __int_as_float(i), 0.0f);
    }
}

// ---------------------------------------------------------------------------
// Kernel 2: blocks [0,TPATCH): per-cell exact top-K via block-gathered SMEM
// candidate list. Blocks [TPATCH, +BEZB): bezier/segment/color precompute.
// Selection key = (d_bits<<32)|idx  (d>=0 float is order-preserving as uint)
// => exact JAX top_k (dist asc, idx tiebreak) via single 64-bit compares.
// ---------------------------------------------------------------------------
__global__ __launch_bounds__(64) void topk_kernel(
    const float* __restrict__ cs,
    const float* __restrict__ ce,
    const float* __restrict__ cc,
    const float* __restrict__ loc,
    const float* __restrict__ color,
    const float* __restrict__ width)
{
    int tid = threadIdx.x;

    if (blockIdx.x >= TPATCH) {
        // ---------------- bezier + segment precompute + color pack ----------
        int n = (blockIdx.x - TPATCH) * 64 + tid;
        if (n >= NS) return;
        float lx = loc[2*n], ly = loc[2*n+1];
        float sx = cs[2*n] + lx, sy = cs[2*n+1] + ly;
        float cx = cc[2*n] + lx, cy = cc[2*n+1] + ly;
        float ex = ce[2*n] + lx, ey = ce[2*n+1] + ly;
        float dsx = sx - cx, dsy = sy - cy;
        float dex = ex - cx, dey = ey - cy;
        const float dt = 1.0f / 9.0f;
        float pxp[SS], pyp[SS];
#pragma unroll
        for (int j = 0; j < SS; j++) {
            float t   = (float)j * dt;
            float omt = 1.0f - t;
            float o2  = omt * omt;
            float t2  = t * t;
            pxp[j] = cx + o2 * dsx + t2 * dex;
            pyp[j] = cy + o2 * dsy + t2 * dey;
        }
#pragma unroll
        for (int s = 0; s < NSEG; s++) {
            float ax = pxp[s],      ay = pyp[s];
            float dx = pxp[s+1]-ax, dy = pyp[s+1]-ay;
            float denom = dx*dx + dy*dy;
            g_seg[n*NSEG + s]  = make_float4(ax, ay, dx, dy);
            g_sinv[n*NSEG + s] = 1.0f / denom;
        }
        g_col4[n] = make_float4(color[n*3], color[n*3+1], color[n*3+2], 0.0f);
        return;
    }

    // ---------------- per-cell top-K ----------------
    __shared__ float4 s_cand[MAXCAND];

    int pb  = blockIdx.x;
    int pby = pb / TGX, pbx = pb % TGX;
    int ci  = pby * PATCH + (tid >> 3);
    int cj  = pbx * PATCH + (tid & 7);
    bool valid = (ci < HC) && (cj < WC);
    int cic = min(ci, HC-1), cjc = min(cj, WC-1);
    float px = (float)cic * STEPC;
    float py = (float)cjc * STEPC;

    // block-uniform bin bbox of this cell patch + margin
    int ci0 = pby * PATCH, ci1 = min(ci0 + PATCH - 1, HC-1);
    int cj0 = pbx * PATCH, cj1 = min(cj0 + PATCH - 1, WC-1);
    int bx0 = min(GB-1, (int)((float)ci0 * STEPC * INV_BINW));
    int bx1 = min(GB-1, (int)((float)ci1 * STEPC * INV_BINW));
    int by0 = min(GB-1, (int)((float)cj0 * STEPC * INV_BINW));
    int by1 = min(GB-1, (int)((float)cj1 * STEPC * INV_BINW));
    int x0u = bx0 - MARGIN, x1u = bx1 + MARGIN;
    int y0u = by0 - MARGIN, y1u = by1 + MARGIN;
    int cxl = max(x0u, 0), cxh = min(x1u, GB-1);
    int cyl = max(y0u, 0), cyh = min(y1u, GB-1);

    // cooperative gather: each bin-row [cyl..cyh] of row xx is contiguous
    int base = 0;
    bool ovf = false;
    for (int xx = cxl; xx <= cxh; xx++) {
        int r0  = g_binoff[xx*GB + cyl];
        int r1  = g_binoff[xx*GB + cyh + 1];
        int len = r1 - r0;
        int use = min(len, MAXCAND - base);
        if (use < len) ovf = true;
        for (int j = tid; j < use; j += 64)
            s_cand[base + j] = g_bpack[r0 + j];
        base += use;
    }
    __syncthreads();
    int cnt = base;

    unsigned long long key[KK];
#pragma unroll
    for (int k = 0; k < KK; k++) key[k] = 0xFFFFFFFFFFFFFFFFull;

    for (int j = 0; j < cnt; j++) {
        float4 c = s_cand[j];               // same address all lanes: broadcast
        float dx = px - c.x, dy = py - c.y;
        float d  = dx*dx + dy*dy;
        unsigned long long pk =
            ((unsigned long long)__float_as_uint(d) << 32) |
            (unsigned int)__float_as_int(c.z);
        if (pk < key[KK-1]) {
#pragma unroll
            for (int k = 0; k < KK; k++) {
                bool cnd = pk < key[k];
                unsigned long long old = key[k];
                key[k] = cnd ? pk : old;
                pk     = cnd ? old : pk;
            }
        }
    }

    // exact termination check: everything ungathered lies outside the swept
    // (unclamped) rect => dist >= m. Fallback: brute scan of all strokes.
    float m = fminf(fminf(px - (float)x0u * BINW, (float)(x1u+1) * BINW - px),
                    fminf(py - (float)y0u * BINW, (float)(y1u+1) * BINW - py));
    float d19 = __uint_as_float((unsigned int)(key[KK-1] >> 32));
    if (d19 >= m * m || ovf) {
#pragma unroll
        for (int k = 0; k < KK; k++) key[k] = 0xFFFFFFFFFFFFFFFFull;
        for (int j = 0; j < NS; j++) {
            float4 c = g_bpack[j];
            float dx = px - c.x, dy = py - c.y;
            float d  = dx*dx + dy*dy;
            unsigned long long pk =
                ((unsigned long long)__float_as_uint(d) << 32) |
                (unsigned int)__float_as_int(c.z);
            if (pk < key[KK-1]) {
#pragma unroll
                for (int k = 0; k < KK; k++) {
                    bool cnd = pk < key[k];
                    unsigned long long old = key[k];
                    key[k] = cnd ? pk : old;
                    pk     = cnd ? old : pk;
                }
            }
        }
    }

    if (valid) {
        int cell = ci * WC + cj;
#pragma unroll
        for (int o = 0; o < KK; o++) {
            int idx = (int)(unsigned int)(key[o] & 0xFFFFFFFFull);
            g_cidx[cell*KK + o] = idx;
            g_cw  [cell*KK + o] = width[idx];
        }
    }
}

// ---------------------------------------------------------------------------
// Kernel 3: per-pixel render. Branch-free streaming softmax. (unchanged)
// ---------------------------------------------------------------------------
__global__ __launch_bounds__(256, 5) void render_kernel(float* __restrict__ out)
{
    int w = blockIdx.x * 8  + threadIdx.x;
    int h = blockIdx.y * 32 + threadIdx.y;

    const float STEPF = 512.0f / 511.0f;
    float px = (float)h * STEPF;
    float py = (float)w * STEPF;

    const float SC = 102.0f / 512.0f;      // exact in fp32
    int ihc = (int)floorf((float)h * SC); if (ihc > HC-1) ihc = HC-1;
    int iwc = (int)floorf((float)w * SC); if (iwc > WC-1) iwc = WC-1;
    int cell = ihc * WC + iwc;

    // bilinear coords for width resize (half-pixel convention, edge clamp)
    float uh = ((float)h + 0.5f) * SC - 0.5f;
    uh = fminf(fmaxf(uh, 0.0f), (float)(HC-1));
    int h0 = (int)uh; float fh = uh - (float)h0; int h1 = min(h0+1, HC-1);
    float uw = ((float)w + 0.5f) * SC - 0.5f;
    uw = fminf(fmaxf(uw, 0.0f), (float)(WC-1));
    int w0 = (int)uw; float fw = uw - (float)w0; int w1 = min(w0+1, WC-1);

    float c00 = (1.0f - fh) * (1.0f - fw);
    float c01 = (1.0f - fh) * fw;
    float c10 = fh * (1.0f - fw);
    float c11 = fh * fw;

    const float* W00 = &g_cw[(h0*WC + w0)*KK];
    const float* W01 = &g_cw[(h0*WC + w1)*KK];
    const float* W10 = &g_cw[(h1*WC + w0)*KK];
    const float* W11 = &g_cw[(h1*WC + w1)*KK];
    const int*   IDX = &g_cidx[cell*KK];

    float M = -FLT_MAX, ssum = 0.0f;
    float a0 = 0.0f, a1 = 0.0f, a2 = 0.0f, bsacc = 0.0f;
    float Dmin = FLT_MAX;

    for (int k = 0; k < KK; k++) {
        int n = __ldg(&IDX[k]);
        const float4* S4 = &g_seg[n*NSEG];
        const float*  SI = &g_sinv[n*NSEG];
        float md = FLT_MAX;
#pragma unroll
        for (int s = 0; s < NSEG; s++) {
            float4 sg = __ldg(&S4[s]);
            float inv = __ldg(&SI[s]);
            float pax = px - sg.x, pay = py - sg.y;
            float t = (sg.z*pax + sg.w*pay) * inv;
            t = fminf(fmaxf(t, 0.0f), 1.0f);
            float cx = sg.x + t*sg.z;
            float cy = sg.y + t*sg.w;
            float dx = px - cx, dy = py - cy;
            md = fminf(md, dx*dx + dy*dy);
        }
        Dmin = fminf(Dmin, md);
        float L = 100000.0f / (1e-8f + md);   // exact div: softmax-sensitive

        float wk = c00 * __ldg(&W00[k]) + c01 * __ldg(&W01[k])
                 + c10 * __ldg(&W10[k]) + c11 * __ldg(&W11[k]);

        float4 col = __ldg(&g_col4[n]);

        float nM = fmaxf(M, L);
        float rr = __expf(M - nM);            // 1.0 when M unchanged
        float e  = __expf(L - nM);
        ssum  = ssum  * rr + e;
        a0    = a0    * rr + e * col.x;
        a1    = a1    * rr + e * col.y;
        a2    = a2    * rr + e * col.z;
        bsacc = bsacc * rr + e * wk;
        M = nM;
    }

    float inv = 1.0f / ssum;
    float bs  = bsacc * inv;
    float x   = bs - Dmin;
    float mask = 1.0f / (1.0f + expf(-x));
    float omm  = 1.0f - mask;

    int base = (h*WW + w) * 3;
    out[base + 0] = a0 * inv * mask + omm * 0.5f;
    out[base + 1] = a1 * inv * mask + omm * 0.5f;
    out[base + 2] = a2 * inv * mask + omm * 0.5f;
}

// ---------------------------------------------------------------------------
// Launch. Inputs (metadata order): curve_s, curve_e, curve_c, color, location, width
// ---------------------------------------------------------------------------
extern "C" void kernel_launch(void* const* d_in, const int* in_sizes, int n_in,
                              void* d_out, int out_size)
{
    const float* curve_s  = (const float*)d_in[0];
    const float* curve_e  = (const float*)d_in[1];
    const float* curve_c  = (const float*)d_in[2];
    const float* color    = (const float*)d_in[3];
    const float* location = (const float*)d_in[4];
    const float* width    = (const float*)d_in[5];
    float* out = (float*)d_out;

    bin_kernel<<<1, 1024>>>(location);

    // blocks [0,169): topk patches; [169,248): bezier/segment/color
    topk_kernel<<<TPATCH + BEZB, 64>>>(curve_s, curve_e, curve_c,
                                       location, color, width);

    dim3 blk(8, 32);
    dim3 grd(WW/8, HH/32);
    render_kernel<<<grd, blk>>>(out);
}